// round 6
// baseline (speedup 1.0000x reference)
#include <cuda_runtime.h>
#include <cuda_bf16.h>
#include <cstdint>

#define NN 10000
#define NE 320000
#define INF 512
#define H1F 256
#define H2F 64
#define NT 79              // 128-row tiles covering NN
#define NPAD (NT * 128)    // 10112

// ---------------- scratch ----------------
__device__ float g_sup1[NN * H1F];
__device__ float g_h1[NN * H1F];
__device__ float g_sup2[NN * H2F];
__device__ int   g_cnt[NN];
__device__ int   g_cur[NN];
__device__ int   g_off[NN + 1];
__device__ int   g_eid[NE];
__device__ __align__(16) __nv_bfloat16 g_zhi[NPAD * H2F];   // rows >= NN stay 0 forever
__device__ __align__(16) __nv_bfloat16 g_zlo[NPAD * H2F];
__device__ __align__(16) __nv_bfloat16 g_xhi[NPAD * INF];
__device__ __align__(16) __nv_bfloat16 g_xlo[NPAD * INF];
__device__ __align__(16) __nv_bfloat16 g_w1thi[H1F * INF];   // [n][k]
__device__ __align__(16) __nv_bfloat16 g_w1tlo[H1F * INF];

// ---------------- f32x2 helpers (layer-2 GEMM) ----------------
__device__ __forceinline__ float2 u2f(unsigned long long u) {
    float2 f;
    asm("mov.b64 {%0,%1}, %2;" : "=f"(f.x), "=f"(f.y) : "l"(u));
    return f;
}
#define FFMA2(acc, a, b) \
    asm("fma.rn.f32x2 %0, %1, %2, %0;" : "+l"(acc) : "l"(a), "l"(b))

// ---------------- mma / async helpers ----------------
__device__ __forceinline__ uint32_t smem_u32(const void* p) {
    uint32_t a;
    asm("{ .reg .u64 t; cvta.to.shared.u64 t, %1; cvt.u32.u64 %0, t; }" : "=r"(a) : "l"(p));
    return a;
}
#define LDSM4(r, addr)                                                          \
    asm volatile("ldmatrix.sync.aligned.m8n8.x4.shared.b16 {%0,%1,%2,%3}, [%4];" \
        : "=r"((r)[0]), "=r"((r)[1]), "=r"((r)[2]), "=r"((r)[3]) : "r"(addr))
#define MMA16816(c, a, b0, b1)                                                  \
    asm volatile("mma.sync.aligned.m16n8k16.row.col.f32.bf16.bf16.f32 "         \
        "{%0,%1,%2,%3},{%4,%5,%6,%7},{%8,%9},{%0,%1,%2,%3};"                    \
        : "+f"((c)[0]), "+f"((c)[1]), "+f"((c)[2]), "+f"((c)[3])                \
        : "r"((a)[0]), "r"((a)[1]), "r"((a)[2]), "r"((a)[3]), "r"(b0), "r"(b1))
#define CP_ASYNC16(saddr, gptr) \
    asm volatile("cp.async.cg.shared.global [%0], [%1], 16;" :: "r"(saddr), "l"(gptr))
#define CP_COMMIT() asm volatile("cp.async.commit_group;")
#define CP_WAIT0()  asm volatile("cp.async.wait_group 0;")

__device__ __forceinline__ float fast_sigmoid(float x) {
    float t;
    asm("tanh.approx.f32 %0, %1;" : "=f"(t) : "f"(x * 0.5f));
    return fmaf(0.5f, t, 0.5f);
}

// ================= CSR build =================
__global__ void count_deg(const int* __restrict__ dst) {
    int e = blockIdx.x * blockDim.x + threadIdx.x;
    if (e < NE) atomicAdd(&g_cnt[dst[e]], 1);
}

__global__ __launch_bounds__(1024) void scan_offsets() {
    __shared__ int wsum[32];
    __shared__ int s_carry;
    const int tid = threadIdx.x;
    const int lane = tid & 31, w = tid >> 5;
    if (tid == 0) s_carry = 0;
    __syncthreads();
    for (int base = 0; base < NN; base += 1024) {
        int i = base + tid;
        int v = (i < NN) ? g_cnt[i] : 0;
        int incl = v;
#pragma unroll
        for (int s = 1; s < 32; s <<= 1) {
            int t = __shfl_up_sync(0xFFFFFFFFu, incl, s);
            if (lane >= s) incl += t;
        }
        if (lane == 31) wsum[w] = incl;
        __syncthreads();
        if (w == 0) {
            int x = wsum[lane];
#pragma unroll
            for (int s = 1; s < 32; s <<= 1) {
                int t = __shfl_up_sync(0xFFFFFFFFu, x, s);
                if (lane >= s) x += t;
            }
            wsum[lane] = x;
        }
        __syncthreads();
        int woff = (w > 0) ? wsum[w - 1] : 0;
        int c0 = s_carry;
        int excl = c0 + woff + incl - v;
        if (i < NN) {
            g_off[i] = excl;
            g_cur[i] = excl;
        }
        __syncthreads();
        if (tid == 0) s_carry = c0 + wsum[31];
        __syncthreads();
    }
    if (tid == 0) g_off[NN] = s_carry;
}

__global__ void fill_buckets(const int* __restrict__ dst) {
    int e = blockIdx.x * blockDim.x + threadIdx.x;
    if (e < NE) {
        int p = atomicAdd(&g_cur[dst[e]], 1);
        g_eid[p] = e;
    }
}

// ================= gather aggregation (fused bias + relu) =================
__global__ __launch_bounds__(256) void gather_h1(
    const float4* __restrict__ sup, const int* __restrict__ esrc,
    const float* __restrict__ ew, const float* __restrict__ bias,
    float4* __restrict__ outp)
{
    int node = blockIdx.x * 4 + (threadIdx.x >> 6);
    int q = threadIdx.x & 63;
    int s0 = g_off[node], s1 = g_off[node + 1];
    float4 acc = make_float4(0.f, 0.f, 0.f, 0.f);
    for (int i = s0; i < s1; i++) {
        int e = g_eid[i];
        float w = ew[e];
        int s = esrc[e];
        float4 v = sup[((size_t)s << 6) + q];
        acc.x += w * v.x; acc.y += w * v.y;
        acc.z += w * v.z; acc.w += w * v.w;
    }
    float4 b = *(const float4*)&bias[q * 4];
    acc.x = fmaxf(acc.x + b.x, 0.f);
    acc.y = fmaxf(acc.y + b.y, 0.f);
    acc.z = fmaxf(acc.z + b.z, 0.f);
    acc.w = fmaxf(acc.w + b.w, 0.f);
    outp[((size_t)node << 6) + q] = acc;
}

// gather_z fused with z hi/lo split
__global__ __launch_bounds__(256) void gather_z(
    const float4* __restrict__ sup, const int* __restrict__ esrc,
    const float* __restrict__ ew, const float* __restrict__ bias,
    float4* __restrict__ outp)
{
    int node = blockIdx.x * 16 + (threadIdx.x >> 4);
    int q = threadIdx.x & 15;
    int s0 = g_off[node], s1 = g_off[node + 1];
    float4 acc = make_float4(0.f, 0.f, 0.f, 0.f);
    for (int i = s0; i < s1; i++) {
        int e = g_eid[i];
        float w = ew[e];
        int s = esrc[e];
        float4 v = sup[((size_t)s << 4) + q];
        acc.x += w * v.x; acc.y += w * v.y;
        acc.z += w * v.z; acc.w += w * v.w;
    }
    float4 b = *(const float4*)&bias[q * 4];
    acc.x = fmaxf(acc.x + b.x, 0.f);
    acc.y = fmaxf(acc.y + b.y, 0.f);
    acc.z = fmaxf(acc.z + b.z, 0.f);
    acc.w = fmaxf(acc.w + b.w, 0.f);
    outp[((size_t)node << 4) + q] = acc;

    int idx = (node << 6) + q * 4;
    __nv_bfloat16 h0 = __float2bfloat16(acc.x);
    __nv_bfloat16 h1v = __float2bfloat16(acc.y);
    __nv_bfloat16 h2 = __float2bfloat16(acc.z);
    __nv_bfloat16 h3 = __float2bfloat16(acc.w);
    __nv_bfloat16 hi4[4] = { h0, h1v, h2, h3 };
    __nv_bfloat16 lo4[4] = {
        __float2bfloat16(acc.x - __bfloat162float(h0)),
        __float2bfloat16(acc.y - __bfloat162float(h1v)),
        __float2bfloat16(acc.z - __bfloat162float(h2)),
        __float2bfloat16(acc.w - __bfloat162float(h3)) };
    *(uint2*)&g_zhi[idx] = *(const uint2*)hi4;
    *(uint2*)&g_zlo[idx] = *(const uint2*)lo4;
}

// ================= split kernels (vectorized) =================
__global__ void split_x4(const float* __restrict__ x) {
    int i4 = blockIdx.x * blockDim.x + threadIdx.x;
    if (i4 >= (NPAD * INF) / 4) return;
    int idx = i4 * 4;
    float4 v;
    if (idx < NN * INF) v = *(const float4*)(x + idx);
    else                v = make_float4(0.f, 0.f, 0.f, 0.f);
    __nv_bfloat16 hi4[4], lo4[4];
    float vv[4] = { v.x, v.y, v.z, v.w };
#pragma unroll
    for (int c = 0; c < 4; c++) {
        hi4[c] = __float2bfloat16(vv[c]);
        lo4[c] = __float2bfloat16(vv[c] - __bfloat162float(hi4[c]));
    }
    *(uint2*)&g_xhi[idx] = *(const uint2*)hi4;
    *(uint2*)&g_xlo[idx] = *(const uint2*)lo4;
}

__global__ void split_w1t(const float* __restrict__ W1) {
    int i4 = blockIdx.x * blockDim.x + threadIdx.x;
    if (i4 >= (INF * H1F) / 4) return;
    int idx = i4 * 4;
    int k = idx >> 8;
    int n = idx & 255;
    float4 v = *(const float4*)(W1 + idx);
    float vv[4] = { v.x, v.y, v.z, v.w };
#pragma unroll
    for (int c = 0; c < 4; c++) {
        __nv_bfloat16 h = __float2bfloat16(vv[c]);
        g_w1thi[(n + c) * INF + k] = h;
        g_w1tlo[(n + c) * INF + k] = __float2bfloat16(vv[c] - __bfloat162float(h));
    }
}

// ================= GEMM1 via mma.sync bf16-split, cp.async 2-stage =================
#define G1_XH 0
#define G1_XL 18432
#define G1_WH 36864
#define G1_WL 46080
#define G1_STAGE 55296
#define G1_SMEM (2 * G1_STAGE)

__device__ __forceinline__ void g1_load_stage(uint32_t sbase, int row0, int col0,
                                              int k0, int tid) {
    const int lrow = tid >> 1, lhalf = tid & 1;
    {
        const char* gh = (const char*)(g_xhi + (size_t)(row0 + lrow) * INF + k0) + lhalf * 64;
        const char* gl = (const char*)(g_xlo + (size_t)(row0 + lrow) * INF + k0) + lhalf * 64;
        uint32_t dh = sbase + G1_XH + lrow * 144 + lhalf * 64;
        uint32_t dl = sbase + G1_XL + lrow * 144 + lhalf * 64;
#pragma unroll
        for (int q = 0; q < 4; q++) {
            CP_ASYNC16(dh + q * 16, gh + q * 16);
            CP_ASYNC16(dl + q * 16, gl + q * 16);
        }
    }
    if (tid < 128) {
        const char* gh = (const char*)(g_w1thi + (size_t)(col0 + lrow) * INF + k0) + lhalf * 64;
        const char* gl = (const char*)(g_w1tlo + (size_t)(col0 + lrow) * INF + k0) + lhalf * 64;
        uint32_t dh = sbase + G1_WH + lrow * 144 + lhalf * 64;
        uint32_t dl = sbase + G1_WL + lrow * 144 + lhalf * 64;
#pragma unroll
        for (int q = 0; q < 4; q++) {
            CP_ASYNC16(dh + q * 16, gh + q * 16);
            CP_ASYNC16(dl + q * 16, gl + q * 16);
        }
    }
}

__global__ __launch_bounds__(256) void gemm1_mma(float* __restrict__ C) {
    extern __shared__ char smem[];
    const int tid = threadIdx.x;
    const int wid = tid >> 5;
    const int lid = tid & 31;
    const int row0 = blockIdx.y * 128;
    const int col0 = blockIdx.x * 64;

    const int wm = wid >> 1, wn = wid & 1;
    const int m0 = wm * 32, n0 = wn * 32;

    float c[2][4][4];
#pragma unroll
    for (int i = 0; i < 2; i++)
#pragma unroll
        for (int j = 0; j < 4; j++)
#pragma unroll
            for (int r = 0; r < 4; r++) c[i][j][r] = 0.f;

    const uint32_t sb = smem_u32(smem);
    const int g8 = lid >> 3;
    const int r8 = lid & 7;

    g1_load_stage(sb, row0, col0, 0, tid);
    CP_COMMIT();

    for (int it = 0; it < 8; it++) {
        CP_WAIT0();
        __syncthreads();
        if (it < 7) {
            g1_load_stage(sb + ((it + 1) & 1) * G1_STAGE, row0, col0, (it + 1) * 64, tid);
            CP_COMMIT();
        }
        const uint32_t st = sb + (it & 1) * G1_STAGE;

#pragma unroll
        for (int ks = 0; ks < 4; ks++) {
            const int kb = ks * 16;
            uint32_t B[2][2][4];
#pragma unroll
            for (int jp = 0; jp < 2; jp++) {
                int rown = n0 + jp * 16 + (g8 >> 1) * 8 + r8;
                int kcol = kb + (g8 & 1) * 8;
                uint32_t a = st + rown * 144 + kcol * 2;
                LDSM4(B[0][jp], a + G1_WH);
                LDSM4(B[1][jp], a + G1_WL);
            }
            uint32_t A[2][4];
#pragma unroll
            for (int i = 0; i < 2; i++) {
                int row = m0 + 16 * i + (g8 & 1) * 8 + r8;
                int kcol = kb + (g8 >> 1) * 8;
                LDSM4(A[i], st + G1_XH + row * 144 + kcol * 2);
            }
#pragma unroll
            for (int i = 0; i < 2; i++)
#pragma unroll
                for (int j = 0; j < 4; j++) {
                    MMA16816(c[i][j], A[i], B[0][j >> 1][(j & 1) * 2], B[0][j >> 1][(j & 1) * 2 + 1]);
                    MMA16816(c[i][j], A[i], B[1][j >> 1][(j & 1) * 2], B[1][j >> 1][(j & 1) * 2 + 1]);
                }
#pragma unroll
            for (int i = 0; i < 2; i++) {
                int row = m0 + 16 * i + (g8 & 1) * 8 + r8;
                int kcol = kb + (g8 >> 1) * 8;
                LDSM4(A[i], st + G1_XL + row * 144 + kcol * 2);
            }
#pragma unroll
            for (int i = 0; i < 2; i++)
#pragma unroll
                for (int j = 0; j < 4; j++)
                    MMA16816(c[i][j], A[i], B[0][j >> 1][(j & 1) * 2], B[0][j >> 1][(j & 1) * 2 + 1]);
        }
    }

    const int g = lid >> 2, t = lid & 3;
#pragma unroll
    for (int i = 0; i < 2; i++)
#pragma unroll
        for (int j = 0; j < 4; j++) {
            int r0 = row0 + m0 + 16 * i + g;
            int cc = col0 + n0 + 8 * j + 2 * t;
            if (r0 < NN)
                *(float2*)&C[(size_t)r0 * H1F + cc] = make_float2(c[i][j][0], c[i][j][1]);
            if (r0 + 8 < NN)
                *(float2*)&C[(size_t)(r0 + 8) * H1F + cc] = make_float2(c[i][j][2], c[i][j][3]);
        }
}

// ================= SGEMM BM=64 BN=32 (layer 2, f32x2) =================
__global__ __launch_bounds__(256) void sgemm_64x32(
    const float* __restrict__ A, const float* __restrict__ B, float* __restrict__ C,
    int M, int N, int K)
{
    __shared__ __align__(16) float  As[16][64];
    __shared__ __align__(16) float2 Bs2[16][32];

    const int tid = threadIdx.x;
    const int tx = tid & 7;
    const int ty = tid >> 3;
    const int row0 = blockIdx.y * 64;
    const int col0 = blockIdx.x * 32;

    unsigned long long acc[4];
#pragma unroll
    for (int j = 0; j < 4; j++) acc[j] = 0ull;

    const int lm = tid >> 2;
    const int lk = (tid & 3) * 4;
    const int bk = tid >> 4;
    const int bn = (tid & 15) * 2;

    for (int k0 = 0; k0 < K; k0 += 16) {
        float4 a0;
        int gm = row0 + lm;
        if (gm < M) a0 = *(const float4*)(A + (size_t)gm * K + k0 + lk);
        else        a0 = make_float4(0.f, 0.f, 0.f, 0.f);
        As[lk + 0][lm] = a0.x; As[lk + 1][lm] = a0.y;
        As[lk + 2][lm] = a0.z; As[lk + 3][lm] = a0.w;

        const float* Bp = B + (size_t)(k0 + bk) * N + col0 + bn;
        float2 bv = *(const float2*)Bp;
        Bs2[bk][bn + 0] = make_float2(bv.x, bv.x);
        Bs2[bk][bn + 1] = make_float2(bv.y, bv.y);
        __syncthreads();

#pragma unroll
        for (int k = 0; k < 16; k++) {
            unsigned long long av = *(const unsigned long long*)&As[k][ty * 2];
            unsigned long long bb[4];
#pragma unroll
            for (int j = 0; j < 4; j++)
                bb[j] = *(const unsigned long long*)&Bs2[k][tx + 8 * j];
#pragma unroll
            for (int j = 0; j < 4; j++)
                FFMA2(acc[j], av, bb[j]);
        }
        __syncthreads();
    }

    int r0 = row0 + ty * 2;
#pragma unroll
    for (int j = 0; j < 4; j++) {
        float2 v = u2f(acc[j]);
        int c = col0 + tx + 8 * j;
        if (r0 < M)     C[(size_t)r0 * N + c]       = v.x;
        if (r0 + 1 < M) C[(size_t)(r0 + 1) * N + c] = v.y;
    }
}

// ================= recon = sigmoid(z @ z^T), symmetric, 2 CTAs/SM =================
#define RC_AH 0
#define RC_AL 18432
#define RC_BH 36864
#define RC_BL 55296
#define RC_SMEM 73728
__global__ __launch_bounds__(256, 2) void recon_mma(float* __restrict__ out) {
    const int bi = blockIdx.y;
    const int bj = blockIdx.x;
    if (bj < bi) return;

    extern __shared__ char smem[];
    const int tid = threadIdx.x;
    const int wid = tid >> 5;
    const int lid = tid & 31;
    const uint32_t sb = smem_u32(smem);

    {
        const int lrow = tid >> 1, lhalf = tid & 1;
        const __nv_bfloat16* srcs[4] = {
            g_zhi + (size_t)bi * 128 * H2F, g_zlo + (size_t)bi * 128 * H2F,
            g_zhi + (size_t)bj * 128 * H2F, g_zlo + (size_t)bj * 128 * H2F };
        const int dsto[4] = { RC_AH, RC_AL, RC_BH, RC_BL };
#pragma unroll
        for (int p = 0; p < 4; p++) {
            const char* s = (const char*)(srcs[p] + (size_t)lrow * H2F) + lhalf * 64;
            uint32_t d = sb + dsto[p] + lrow * 144 + lhalf * 64;
#pragma unroll
            for (int q = 0; q < 4; q++) CP_ASYNC16(d + q * 16, s + q * 16);
        }
        CP_COMMIT();
        CP_WAIT0();
    }
    __syncthreads();

    const int wm = wid >> 2, wn = wid & 3;
    const int m0 = wm * 64, n0 = wn * 32;
    const int g8 = lid >> 3, r8 = lid & 7;

    float c[4][4][4];
#pragma unroll
    for (int i = 0; i < 4; i++)
#pragma unroll
        for (int j = 0; j < 4; j++)
#pragma unroll
            for (int r = 0; r < 4; r++) c[i][j][r] = 0.f;

#pragma unroll
    for (int ks = 0; ks < 4; ks++) {
        const int kb = ks * 16;
        uint32_t B[2][2][4];
#pragma unroll
        for (int jp = 0; jp < 2; jp++) {
            int rown = n0 + jp * 16 + (g8 >> 1) * 8 + r8;
            int kcol = kb + (g8 & 1) * 8;
            uint32_t a = sb + rown * 144 + kcol * 2;
            LDSM4(B[0][jp], a + RC_BH);
            LDSM4(B[1][jp], a + RC_BL);
        }
        uint32_t A[4][4];
#pragma unroll
        for (int i = 0; i < 4; i++) {
            int row = m0 + 16 * i + (g8 & 1) * 8 + r8;
            int kcol = kb + (g8 >> 1) * 8;
            LDSM4(A[i], sb + RC_AH + row * 144 + kcol * 2);
        }
#pragma unroll
        for (int i = 0; i < 4; i++)
#pragma unroll
            for (int j = 0; j < 4; j++) {
                MMA16816(c[i][j], A[i], B[0][j >> 1][(j & 1) * 2], B[0][j >> 1][(j & 1) * 2 + 1]);
                MMA16816(c[i][j], A[i], B[1][j >> 1][(j & 1) * 2], B[1][j >> 1][(j & 1) * 2 + 1]);
            }
#pragma unroll
        for (int i = 0; i < 4; i++) {
            int row = m0 + 16 * i + (g8 & 1) * 8 + r8;
            int kcol = kb + (g8 >> 1) * 8;
            LDSM4(A[i], sb + RC_AL + row * 144 + kcol * 2);
        }
#pragma unroll
        for (int i = 0; i < 4; i++)
#pragma unroll
            for (int j = 0; j < 4; j++)
                MMA16816(c[i][j], A[i], B[0][j >> 1][(j & 1) * 2], B[0][j >> 1][(j & 1) * 2 + 1]);
    }

    const int g = lid >> 2, t = lid & 3;
    const bool mirror = (bj > bi);
#pragma unroll
    for (int i = 0; i < 4; i++) {
        int r0 = bi * 128 + m0 + 16 * i + g;
        int r1 = r0 + 8;
#pragma unroll
        for (int j = 0; j < 4; j++) {
            int cc = bj * 128 + n0 + 8 * j + 2 * t;
            float s0 = fast_sigmoid(c[i][j][0]);
            float s1 = fast_sigmoid(c[i][j][1]);
            float s2 = fast_sigmoid(c[i][j][2]);
            float s3 = fast_sigmoid(c[i][j][3]);
            if (cc < NN) {
                if (r0 < NN) *(float2*)&out[(size_t)r0 * NN + cc] = make_float2(s0, s1);
                if (r1 < NN) *(float2*)&out[(size_t)r1 * NN + cc] = make_float2(s2, s3);
                if (mirror) {
                    if (r0 < NN) {
                        out[(size_t)cc * NN + r0]       = s0;
                        out[(size_t)(cc + 1) * NN + r0] = s1;
                    }
                    if (r1 < NN) {
                        out[(size_t)cc * NN + r1]       = s2;
                        out[(size_t)(cc + 1) * NN + r1] = s3;
                    }
                }
            }
        }
    }
}

// ================= launch =================
extern "C" void kernel_launch(void* const* d_in, const int* in_sizes, int n_in,
                              void* d_out, int out_size)
{
    const float* x    = (const float*)d_in[0];
    const float* W1   = (const float*)d_in[1];
    const float* b1   = (const float*)d_in[2];
    const float* W2   = (const float*)d_in[3];
    const float* b2   = (const float*)d_in[4];
    const float* ew   = (const float*)d_in[5];
    const int*   esrc = (const int*)d_in[6];
    const int*   edst = (const int*)d_in[7];

    float* out   = (float*)d_out;
    float* z     = out;               // [10000, 64]
    float* recon = out + NN * H2F;    // [10000, 10000]

    float *sup1, *h1, *sup2;
    int *cnt;
    cudaGetSymbolAddress((void**)&sup1, g_sup1);
    cudaGetSymbolAddress((void**)&h1,   g_h1);
    cudaGetSymbolAddress((void**)&sup2, g_sup2);
    cudaGetSymbolAddress((void**)&cnt,  g_cnt);

    cudaFuncSetAttribute(gemm1_mma, cudaFuncAttributeMaxDynamicSharedMemorySize, G1_SMEM);
    cudaFuncSetAttribute(recon_mma, cudaFuncAttributeMaxDynamicSharedMemorySize, RC_SMEM);

    // independent prep first (keeps gemm1 at the ncu capture slot)
    cudaMemsetAsync(cnt, 0, NN * sizeof(int));
    split_x4<<<((NPAD * INF) / 4 + 255) / 256, 256>>>(x);
    split_w1t<<<((INF * H1F) / 4 + 255) / 256, 256>>>(W1);
    count_deg<<<NE / 256, 256>>>(edst);

    // layer 1 GEMM (5th launch -> profiled)
    gemm1_mma<<<dim3(H1F / 64, NT), 256, G1_SMEM>>>(sup1);

    // finish CSR, then aggregate
    scan_offsets<<<1, 1024>>>();
    fill_buckets<<<NE / 256, 256>>>(edst);
    gather_h1<<<NN / 4, 256>>>((const float4*)sup1, esrc, ew, b1, (float4*)h1);

    // layer 2
    sgemm_64x32<<<dim3(H2F / 32, (NN + 63) / 64), 256>>>(h1, W2, sup2, NN, H2F, H1F);
    gather_z<<<NN / 16, 256>>>((const float4*)sup2, esrc, ew, b2, (float4*)z);

    // decoder
    recon_mma<<<dim3(NT, NT), 256, RC_SMEM>>>(recon);
}